// round 16
// baseline (speedup 1.0000x reference)
#include <cuda_runtime.h>
#include <cuda_bf16.h>
#include <cuda_fp16.h>
#include <cstdint>

#define BATCH 2
#define SEQ   2048
#define EMB   1024
#define NH    16
#define HD    64
#define M_TOT (BATCH*SEQ)   // 4096
#define N_TOT (3*EMB)       // 3072
#define K_TOT EMB           // 1024

// ---------------------------------------------------------------------------
// Device scratch (allocation-free): Q/K/V single fp16 planes in [B,H,T,D]
// ---------------------------------------------------------------------------
__device__ __half g_qf[(size_t)BATCH*NH*SEQ*HD];
__device__ __half g_kf[(size_t)BATCH*NH*SEQ*HD];
__device__ __half g_vf[(size_t)BATCH*NH*SEQ*HD];

__device__ __half g_xf[(size_t)M_TOT*K_TOT];    // X fp16 single plane
__device__ __half g_wtf[(size_t)N_TOT*K_TOT];   // W^T fp16 single plane [N,K]

// ---------------------------------------------------------------------------
// Helpers
// ---------------------------------------------------------------------------
__device__ __forceinline__ uint32_t smem_u32(const void* p) {
    uint32_t a;
    asm("{ .reg .u64 t; cvta.to.shared.u64 t, %1; cvt.u32.u64 %0, t; }" : "=r"(a) : "l"(p));
    return a;
}

__device__ __forceinline__ void cp_async16(uint32_t s, const void* g) {
    asm volatile("cp.async.cg.shared.global [%0], [%1], 16;" :: "r"(s), "l"(g) : "memory");
}
#define CP_COMMIT() asm volatile("cp.async.commit_group;" ::: "memory")
#define CP_WAIT(n)  asm volatile("cp.async.wait_group %0;" :: "n"(n) : "memory")

__device__ __forceinline__ void ldsm_x4(uint32_t& r0, uint32_t& r1, uint32_t& r2,
                                        uint32_t& r3, uint32_t addr) {
    asm volatile("ldmatrix.sync.aligned.m8n8.x4.shared.b16 {%0,%1,%2,%3}, [%4];"
                 : "=r"(r0), "=r"(r1), "=r"(r2), "=r"(r3) : "r"(addr));
}

__device__ __forceinline__ void ldsm_x4_t(uint32_t& r0, uint32_t& r1, uint32_t& r2,
                                          uint32_t& r3, uint32_t addr) {
    asm volatile("ldmatrix.sync.aligned.m8n8.x4.trans.shared.b16 {%0,%1,%2,%3}, [%4];"
                 : "=r"(r0), "=r"(r1), "=r"(r2), "=r"(r3) : "r"(addr));
}

__device__ __forceinline__ void mma_16816h(float& c0, float& c1, float& c2, float& c3,
                                           uint32_t a0, uint32_t a1, uint32_t a2, uint32_t a3,
                                           uint32_t b0, uint32_t b1) {
    asm volatile(
        "mma.sync.aligned.m16n8k16.row.col.f32.f16.f16.f32 "
        "{%0,%1,%2,%3}, {%4,%5,%6,%7}, {%8,%9}, {%0,%1,%2,%3};"
        : "+f"(c0), "+f"(c1), "+f"(c2), "+f"(c3)
        : "r"(a0), "r"(a1), "r"(a2), "r"(a3), "r"(b0), "r"(b1));
}
// D != C form with C = {0,0,0,0}: initializes accumulators without MOVs.
__device__ __forceinline__ void mma_16816h_init(float& d0, float& d1, float& d2, float& d3,
                                                uint32_t a0, uint32_t a1, uint32_t a2, uint32_t a3,
                                                uint32_t b0, uint32_t b1) {
    asm volatile(
        "mma.sync.aligned.m16n8k16.row.col.f32.f16.f16.f32 "
        "{%0,%1,%2,%3}, {%4,%5,%6,%7}, {%8,%9}, {%10,%10,%10,%10};"
        : "=f"(d0), "=f"(d1), "=f"(d2), "=f"(d3)
        : "r"(a0), "r"(a1), "r"(a2), "r"(a3), "r"(b0), "r"(b1), "f"(0.f));
}
#define MMA4H(S, A, B0, B1) \
    mma_16816h((S)[0], (S)[1], (S)[2], (S)[3], (A)[0], (A)[1], (A)[2], (A)[3], (B0), (B1))
#define MMA4HI(S, A, B0, B1) \
    mma_16816h_init((S)[0], (S)[1], (S)[2], (S)[3], (A)[0], (A)[1], (A)[2], (A)[3], (B0), (B1))

__device__ __forceinline__ float ex2f(float x) {
    float y;
    asm("ex2.approx.f32 %0, %1;" : "=f"(y) : "f"(x));
    return y;
}

// XOR swizzle for 128B-row tiles: r = row, c = 16B-chunk index (0..7)
#define SWZ(r, c) ((uint32_t)((r) * 128 + ((((c) ^ ((r) & 7))) << 4)))

// ---------------------------------------------------------------------------
// Convert kernels: fp32 -> fp16 single plane (W also transposed to [N,K])
// ---------------------------------------------------------------------------
__global__ void conv_x(const float* __restrict__ x) {
    int i = blockIdx.x * 256 + threadIdx.x;      // float4 index
    float4 v = ((const float4*)x)[i];
    __half2 a = __floats2half2_rn(v.x, v.y);
    __half2 b = __floats2half2_rn(v.z, v.w);
    ((__half2*)g_xf)[2 * i]     = a;
    ((__half2*)g_xf)[2 * i + 1] = b;
}

__global__ void conv_w(const float* __restrict__ w) {
    __shared__ float t[32][33];
    int nb = blockIdx.x * 32, kb = blockIdx.y * 32;
    int tx = threadIdx.x, ty = threadIdx.y;      // (32, 8)
    #pragma unroll
    for (int r = ty; r < 32; r += 8)
        t[r][tx] = w[(size_t)(kb + r) * N_TOT + nb + tx];
    __syncthreads();
    #pragma unroll
    for (int r = ty; r < 32; r += 8)
        g_wtf[(size_t)(nb + r) * K_TOT + kb + tx] = __float2half_rn(t[tx][r]);
}

// ---------------------------------------------------------------------------
// HMMA QKV GEMM (fp16 1-term): CTA 128(M) x 128(N), 8 warps (32x64),
// k-chunk 64 (128B rows, XOR swizzle), 3-stage cp.async pipeline, 2 CTAs/SM.
// Epilogue: Q/K/V -> single fp16 planes [B,H,T,D]; Q scaled by 0.125*log2e.
// ---------------------------------------------------------------------------
#define OFF_A 0
#define OFF_B 16384
#define BUF_B 32768

__global__ __launch_bounds__(256, 2) void qkv_tc(const float* __restrict__ bias) {
    extern __shared__ __align__(1024) char smem[];
    const uint32_t sbase = smem_u32(smem);
    const int tid  = threadIdx.x;
    const int lane = tid & 31;
    const int wid  = tid >> 5;
    const int wm   = wid >> 1;        // 0..3 (m 32-blocks)
    const int wn   = wid & 1;         // 0..1 (n 64-blocks)
    const int bnB  = blockIdx.x;      // 0..23
    const int bmB  = blockIdx.y;      // 0..31

    const __half* Xf = g_xf  + (size_t)(bmB * 128) * K_TOT;
    const __half* Wf = g_wtf + (size_t)(bnB * 128) * K_TOT;

    auto load_tiles = [&](int ch, int buf) {
        uint32_t sb = sbase + buf * BUF_B;
        #pragma unroll
        for (int it = 0; it < 4; it++) {          // A: 128 rows x 128B
            int f = it * 256 + tid;
            int r = f >> 3, c = f & 7;
            cp_async16(sb + OFF_A + SWZ(r, c), Xf + (size_t)r * K_TOT + ch * 64 + c * 8);
        }
        #pragma unroll
        for (int it = 0; it < 4; it++) {          // B: 128 rows x 128B
            int f = it * 256 + tid;
            int r = f >> 3, c = f & 7;
            cp_async16(sb + OFF_B + SWZ(r, c), Wf + (size_t)r * K_TOT + ch * 64 + c * 8);
        }
        CP_COMMIT();
    };

    float acc[2][8][4];   // [am 16-row][bn 8-col][frag]
    #pragma unroll
    for (int i = 0; i < 2; i++)
        #pragma unroll
        for (int j = 0; j < 8; j++)
            #pragma unroll
            for (int c = 0; c < 4; c++) acc[i][j][c] = 0.f;

    load_tiles(0, 0);
    load_tiles(1, 1);

    const int NCH = K_TOT / 64;   // 16
    for (int ch = 0; ch < NCH; ch++) {
        const int buf = ch % 3;
        if (ch + 2 < NCH) { load_tiles(ch + 2, (ch + 2) % 3); CP_WAIT(2); }
        else if (ch + 1 < NCH) { CP_WAIT(1); }
        else { CP_WAIT(0); }
        __syncthreads();

        const uint32_t sbuf = sbase + buf * BUF_B;
        #pragma unroll
        for (int kh = 0; kh < 4; kh++) {
            uint32_t ah[2][4];
            #pragma unroll
            for (int am = 0; am < 2; am++) {
                int row = wm * 32 + am * 16 + (lane & 15);
                int chn = kh * 2 + (lane >> 4);
                ldsm_x4(ah[am][0], ah[am][1], ah[am][2], ah[am][3],
                        sbuf + OFF_A + SWZ(row, chn));
            }
            #pragma unroll
            for (int bp = 0; bp < 4; bp++) {
                int row = wn * 64 + bp * 16 + ((lane >> 4) << 3) + (lane & 7);
                int chn = kh * 2 + ((lane >> 3) & 1);
                uint32_t b0, b1, b2, b3;
                ldsm_x4(b0, b1, b2, b3, sbuf + OFF_B + SWZ(row, chn));
                const int nA = bp * 2, nB = nA + 1;
                #pragma unroll
                for (int am = 0; am < 2; am++) MMA4H(acc[am][nA], ah[am], b0, b1);
                #pragma unroll
                for (int am = 0; am < 2; am++) MMA4H(acc[am][nB], ah[am], b2, b3);
            }
        }
        __syncthreads();
    }

    // Epilogue: bias; Q scaled by 0.125*log2e; Q/K/V -> single fp16 planes.
    const int mq = lane >> 2;
    const int nq = (lane & 3) * 2;
    const int nbase = bnB * 128 + wn * 64;       // 64-aligned: p uniform per warp
    const int p = nbase >> 10;
    __half* dst = (p == 0) ? g_qf : (p == 1) ? g_kf : g_vf;
    const float sc = (p == 0) ? 0.18033688011112042f : 1.0f;   // 0.125*log2(e)

    #pragma unroll
    for (int bn = 0; bn < 8; bn++) {
        int n = nbase + bn * 8 + nq;
        float2 bb = *(const float2*)(bias + n);
        int cc = n & 1023;
        int hh = cc >> 6, d = cc & 63;
        #pragma unroll
        for (int am = 0; am < 2; am++) {
            #pragma unroll
            for (int half = 0; half < 2; half++) {
                int m = bmB * 128 + wm * 32 + am * 16 + mq + half * 8;
                int bi = m >> 11, t = m & 2047;
                float vx = (acc[am][bn][half * 2]     + bb.x) * sc;
                float vy = (acc[am][bn][half * 2 + 1] + bb.y) * sc;
                __half2 hv = __floats2half2_rn(vx, vy);
                size_t idx = ((size_t)(bi * NH + hh) * SEQ + t) * HD + d;
                *(uint32_t*)(dst + idx) = *reinterpret_cast<uint32_t*>(&hv);
            }
        }
    }
}

// ---------------------------------------------------------------------------
// Tensor-core flash attention, fp16 1-term S and PV, exp2 domain.
// BK=128: each loop iteration processes a 128-row K/V block so all per-block
// fixed costs (shfl reductions, l/m/vote/rescale, CP_WAIT+barrier, mask pass)
// are paid once per 128 columns. Mask only on the last block. LPT, 3 CTAs/SM.
// CTA: 64 Q rows, 4 warps.
// ---------------------------------------------------------------------------
#define KVT2   16384            // one 128-row x 128B plane
#define KVBUF  (2 * KVT2)       // Kf, Vf = 32768
#define KVOFF  8192             // after Qf (8192)
#define ATTN_SMEM (KVOFF + 2 * KVBUF)   // 73728

__global__ __launch_bounds__(128, 3) void attn_mma(float* __restrict__ out) {
    extern __shared__ __align__(1024) char smem[];
    const uint32_t sb = smem_u32(smem);
    const int tid = threadIdx.x, lane = tid & 31, wid = tid >> 5;
    const int qt = (int)gridDim.x - 1 - (int)blockIdx.x;   // LPT: heavy first
    const int hh = blockIdx.y, bb = blockIdx.z;

    const size_t head = (size_t)(bb * NH + hh) * SEQ * HD;
    const char* Qfg = (const char*)(g_qf + head + (size_t)qt * 64 * HD);
    const char* Kfg = (const char*)(g_kf + head);
    const char* Vfg = (const char*)(g_vf + head);

    // Q -> smem (64 rows x 128B)
    #pragma unroll
    for (int i = 0; i < 4; i++) {
        int f = i * 128 + tid;
        int r = f >> 3, c = f & 7;
        cp_async16(sb + SWZ(r, c), Qfg + r * 128 + c * 16);
    }
    CP_COMMIT();

    // Load one 128-row K/V block
    auto load_kv = [&](int kt, int buf) {
        uint32_t base = sb + KVOFF + buf * KVBUF;
        size_t go0 = (size_t)kt * 128 * 128;     // 128 rows x 128 B
        #pragma unroll
        for (int i = 0; i < 8; i++) {
            int f = i * 128 + tid;
            int r = f >> 3, c = f & 7;
            uint32_t sw = SWZ(r, c);
            size_t go = go0 + r * 128 + c * 16;
            cp_async16(base + sw,        Kfg + go);
            cp_async16(base + KVT2 + sw, Vfg + go);
        }
        CP_COMMIT();
    };

    const int nkt = (qt + 2) >> 1;   // ceil((qt+1)*64 / 128)
    load_kv(0, 0);
    CP_WAIT(0);
    __syncthreads();

    // Q fragments (resident)
    uint32_t qf[4][4];
    {
        int row = wid * 16 + (lane & 15);
        #pragma unroll
        for (int ks = 0; ks < 4; ks++) {
            int chn = ks * 2 + (lane >> 4);
            ldsm_x4(qf[ks][0], qf[ks][1], qf[ks][2], qf[ks][3], sb + SWZ(row, chn));
        }
    }

    float o[8][4];
    #pragma unroll
    for (int nt = 0; nt < 8; nt++)
        #pragma unroll
        for (int c = 0; c < 4; c++) o[nt][c] = 0.f;
    float m0 = -1e30f, m1 = -1e30f, l0 = 0.f, l1 = 0.f;

    const int grow = qt * 64 + wid * 16 + (lane >> 2);   // global Q row (and +8)

    for (int kt = 0; kt < nkt; kt++) {
        const int buf = kt & 1;
        const bool has_next = (kt + 1 < nkt);
        if (has_next) load_kv(kt + 1, buf ^ 1);   // async, lands during compute

        // ---- S = Q K^T over 128 K rows (16 n-tiles of 8 cols) ----
        float sA[16][4];
        {
            uint32_t kbase = sb + KVOFF + buf * KVBUF;
            const int krbase = ((lane >> 4) << 3) + (lane & 7);
            #pragma unroll
            for (int ks = 0; ks < 4; ks++) {
                const int chn = ks * 2 + ((lane >> 3) & 1);
                #pragma unroll
                for (int rg = 0; rg < 8; rg++) {
                    uint32_t k0, k1, k2, k3;
                    ldsm_x4(k0, k1, k2, k3, kbase + SWZ(rg * 16 + krbase, chn));
                    if (ks == 0) {
                        MMA4HI(sA[rg * 2],     qf[0], k0, k1);
                        MMA4HI(sA[rg * 2 + 1], qf[0], k2, k3);
                    } else {
                        MMA4H(sA[rg * 2],     qf[ks], k0, k1);
                        MMA4H(sA[rg * 2 + 1], qf[ks], k2, k3);
                    }
                }
            }
        }

        // ---- causal mask (last block only) ----
        if (kt == nkt - 1) {
            #pragma unroll
            for (int nt = 0; nt < 16; nt++) {
                int j0 = kt * 128 + nt * 8 + (lane & 3) * 2;
                if (j0     > grow)     sA[nt][0] = -1e30f;
                if (j0 + 1 > grow)     sA[nt][1] = -1e30f;
                if (j0     > grow + 8) sA[nt][2] = -1e30f;
                if (j0 + 1 > grow + 8) sA[nt][3] = -1e30f;
            }
        }

        // ---- online softmax in exp2 domain (rows grow, grow+8) ----
        float mx0 = -1e30f, mx1 = -1e30f;
        #pragma unroll
        for (int nt = 0; nt < 16; nt++) {
            mx0 = fmaxf(mx0, fmaxf(sA[nt][0], sA[nt][1]));
            mx1 = fmaxf(mx1, fmaxf(sA[nt][2], sA[nt][3]));
        }
        mx0 = fmaxf(mx0, __shfl_xor_sync(0xffffffffu, mx0, 1));
        mx0 = fmaxf(mx0, __shfl_xor_sync(0xffffffffu, mx0, 2));
        mx1 = fmaxf(mx1, __shfl_xor_sync(0xffffffffu, mx1, 1));
        mx1 = fmaxf(mx1, __shfl_xor_sync(0xffffffffu, mx1, 2));
        float mn0 = fmaxf(m0, mx0), mn1 = fmaxf(m1, mx1);
        bool resc = (mn0 > m0) || (mn1 > m1);

        float t0 = 0.f, t1 = 0.f;
        #pragma unroll
        for (int nt = 0; nt < 16; nt++) {
            sA[nt][0] = ex2f(sA[nt][0] - mn0); t0 += sA[nt][0];
            sA[nt][1] = ex2f(sA[nt][1] - mn0); t0 += sA[nt][1];
            sA[nt][2] = ex2f(sA[nt][2] - mn1); t1 += sA[nt][2];
            sA[nt][3] = ex2f(sA[nt][3] - mn1); t1 += sA[nt][3];
        }
        t0 += __shfl_xor_sync(0xffffffffu, t0, 1);
        t0 += __shfl_xor_sync(0xffffffffu, t0, 2);
        t1 += __shfl_xor_sync(0xffffffffu, t1, 1);
        t1 += __shfl_xor_sync(0xffffffffu, t1, 2);
        if (__any_sync(0xffffffffu, resc)) {
            float cr0 = ex2f(m0 - mn0), cr1 = ex2f(m1 - mn1);
            l0 = l0 * cr0 + t0;
            l1 = l1 * cr1 + t1;
            #pragma unroll
            for (int nt = 0; nt < 8; nt++) {
                o[nt][0] *= cr0; o[nt][1] *= cr0;
                o[nt][2] *= cr1; o[nt][3] *= cr1;
            }
        } else {
            l0 += t0; l1 += t1;
        }
        m0 = mn0; m1 = mn1;

        // ---- O += P V over 128 V rows (8 k-groups of 16) ----
        {
            uint32_t vbase = sb + KVOFF + buf * KVBUF + KVT2;
            const int vrbase = ((lane >> 3) & 1) * 8 + (lane & 7);
            #pragma unroll
            for (int t = 0; t < 8; t++) {
                // P fragment for k-group t (cols t*16..t*16+15) from sA tiles 2t, 2t+1
                uint32_t ph[4];
                {
                    __half2 a = __floats2half2_rn(sA[2 * t][0],     sA[2 * t][1]);
                    __half2 b = __floats2half2_rn(sA[2 * t][2],     sA[2 * t][3]);
                    __half2 c = __floats2half2_rn(sA[2 * t + 1][0], sA[2 * t + 1][1]);
                    __half2 d = __floats2half2_rn(sA[2 * t + 1][2], sA[2 * t + 1][3]);
                    ph[0] = *reinterpret_cast<uint32_t*>(&a);
                    ph[1] = *reinterpret_cast<uint32_t*>(&b);
                    ph[2] = *reinterpret_cast<uint32_t*>(&c);
                    ph[3] = *reinterpret_cast<uint32_t*>(&d);
                }
                const int vrow = t * 16 + vrbase;
                #pragma unroll
                for (int gp = 0; gp < 2; gp++) {
                    const int g0 = gp * 2, g1 = gp * 2 + 1;
                    uint32_t sw0 = SWZ(vrow, g0 * 2 + (lane >> 4));
                    uint32_t sw1 = SWZ(vrow, g1 * 2 + (lane >> 4));
                    uint32_t v0, v1, v2, v3, u0, u1, u2, u3;
                    ldsm_x4_t(v0, v1, v2, v3, vbase + sw0);
                    ldsm_x4_t(u0, u1, u2, u3, vbase + sw1);
                    MMA4H(o[2 * g0],     ph, v0, v1);
                    MMA4H(o[2 * g0 + 1], ph, v2, v3);
                    MMA4H(o[2 * g1],     ph, u0, u1);
                    MMA4H(o[2 * g1 + 1], ph, u2, u3);
                }
            }
        }

        if (has_next) {
            CP_WAIT(0);          // kv(kt+1) landed
            __syncthreads();     // all warps done reading buf before reuse
        }
    }

    // ---- epilogue ----
    float il0 = 1.f / l0, il1 = 1.f / l1;
    #pragma unroll
    for (int nt = 0; nt < 8; nt++) {
        int d = nt * 8 + (lane & 3) * 2;
        float2 u0 = make_float2(o[nt][0] * il0, o[nt][1] * il0);
        float2 u1 = make_float2(o[nt][2] * il1, o[nt][3] * il1);
        *(float2*)(out + ((size_t)(bb * SEQ + grow)     * EMB) + hh * 64 + d) = u0;
        *(float2*)(out + ((size_t)(bb * SEQ + grow + 8) * EMB) + hh * 64 + d) = u1;
    }
}

// ---------------------------------------------------------------------------
extern "C" void kernel_launch(void* const* d_in, const int* in_sizes, int n_in,
                              void* d_out, int out_size) {
    const float* x    = (const float*)d_in[0];
    const float* w    = (const float*)d_in[1];
    const float* bias = (const float*)d_in[2];
    float* out = (float*)d_out;

    conv_x<<<M_TOT * K_TOT / (256 * 4), 256>>>(x);
    conv_w<<<dim3(N_TOT / 32, K_TOT / 32), dim3(32, 8)>>>(w);

    const int gemm_smem = 3 * BUF_B;   // 98304 B
    cudaFuncSetAttribute(qkv_tc, cudaFuncAttributeMaxDynamicSharedMemorySize, gemm_smem);
    qkv_tc<<<dim3(N_TOT / 128, M_TOT / 128), 256, gemm_smem>>>(bias);

    cudaFuncSetAttribute(attn_mma, cudaFuncAttributeMaxDynamicSharedMemorySize, ATTN_SMEM);
    attn_mma<<<dim3(SEQ / 64, NH, BATCH), 128, ATTN_SMEM>>>(out);
}

// round 17
// speedup vs baseline: 1.0329x; 1.0329x over previous
#include <cuda_runtime.h>
#include <cuda_bf16.h>
#include <cuda_fp16.h>
#include <cstdint>

#define BATCH 2
#define SEQ   2048
#define EMB   1024
#define NH    16
#define HD    64
#define M_TOT (BATCH*SEQ)   // 4096
#define N_TOT (3*EMB)       // 3072
#define K_TOT EMB           // 1024

// ---------------------------------------------------------------------------
// Device scratch (allocation-free): Q/K/V single fp16 planes in [B,H,T,D]
// ---------------------------------------------------------------------------
__device__ __half g_qf[(size_t)BATCH*NH*SEQ*HD];
__device__ __half g_kf[(size_t)BATCH*NH*SEQ*HD];
__device__ __half g_vf[(size_t)BATCH*NH*SEQ*HD];

__device__ __half g_xf[(size_t)M_TOT*K_TOT];    // X fp16 single plane
__device__ __half g_wtf[(size_t)N_TOT*K_TOT];   // W^T fp16 single plane [N,K]

// ---------------------------------------------------------------------------
// Helpers
// ---------------------------------------------------------------------------
__device__ __forceinline__ uint32_t smem_u32(const void* p) {
    uint32_t a;
    asm("{ .reg .u64 t; cvta.to.shared.u64 t, %1; cvt.u32.u64 %0, t; }" : "=r"(a) : "l"(p));
    return a;
}

__device__ __forceinline__ void cp_async16(uint32_t s, const void* g) {
    asm volatile("cp.async.cg.shared.global [%0], [%1], 16;" :: "r"(s), "l"(g) : "memory");
}
#define CP_COMMIT() asm volatile("cp.async.commit_group;" ::: "memory")
#define CP_WAIT(n)  asm volatile("cp.async.wait_group %0;" :: "n"(n) : "memory")

__device__ __forceinline__ void ldsm_x4(uint32_t& r0, uint32_t& r1, uint32_t& r2,
                                        uint32_t& r3, uint32_t addr) {
    asm volatile("ldmatrix.sync.aligned.m8n8.x4.shared.b16 {%0,%1,%2,%3}, [%4];"
                 : "=r"(r0), "=r"(r1), "=r"(r2), "=r"(r3) : "r"(addr));
}

__device__ __forceinline__ void ldsm_x4_t(uint32_t& r0, uint32_t& r1, uint32_t& r2,
                                          uint32_t& r3, uint32_t addr) {
    asm volatile("ldmatrix.sync.aligned.m8n8.x4.trans.shared.b16 {%0,%1,%2,%3}, [%4];"
                 : "=r"(r0), "=r"(r1), "=r"(r2), "=r"(r3) : "r"(addr));
}

__device__ __forceinline__ void mma_16816h(float& c0, float& c1, float& c2, float& c3,
                                           uint32_t a0, uint32_t a1, uint32_t a2, uint32_t a3,
                                           uint32_t b0, uint32_t b1) {
    asm volatile(
        "mma.sync.aligned.m16n8k16.row.col.f32.f16.f16.f32 "
        "{%0,%1,%2,%3}, {%4,%5,%6,%7}, {%8,%9}, {%0,%1,%2,%3};"
        : "+f"(c0), "+f"(c1), "+f"(c2), "+f"(c3)
        : "r"(a0), "r"(a1), "r"(a2), "r"(a3), "r"(b0), "r"(b1));
}
// D != C form with C = {0,0,0,0}: initializes accumulators without MOVs.
__device__ __forceinline__ void mma_16816h_init(float& d0, float& d1, float& d2, float& d3,
                                                uint32_t a0, uint32_t a1, uint32_t a2, uint32_t a3,
                                                uint32_t b0, uint32_t b1) {
    asm volatile(
        "mma.sync.aligned.m16n8k16.row.col.f32.f16.f16.f32 "
        "{%0,%1,%2,%3}, {%4,%5,%6,%7}, {%8,%9}, {%10,%10,%10,%10};"
        : "=f"(d0), "=f"(d1), "=f"(d2), "=f"(d3)
        : "r"(a0), "r"(a1), "r"(a2), "r"(a3), "r"(b0), "r"(b1), "f"(0.f));
}
#define MMA4H(S, A, B0, B1) \
    mma_16816h((S)[0], (S)[1], (S)[2], (S)[3], (A)[0], (A)[1], (A)[2], (A)[3], (B0), (B1))
#define MMA4HI(S, A, B0, B1) \
    mma_16816h_init((S)[0], (S)[1], (S)[2], (S)[3], (A)[0], (A)[1], (A)[2], (A)[3], (B0), (B1))

__device__ __forceinline__ float ex2f(float x) {
    float y;
    asm("ex2.approx.f32 %0, %1;" : "=f"(y) : "f"(x));
    return y;
}

// XOR swizzle for 128B-row tiles: r = row, c = 16B-chunk index (0..7)
#define SWZ(r, c) ((uint32_t)((r) * 128 + ((((c) ^ ((r) & 7))) << 4)))

// ---------------------------------------------------------------------------
// Merged convert kernel: blocks [0,4096) do X; [4096, 4096+3072) do W^T.
// ---------------------------------------------------------------------------
__global__ void conv_xw(const float* __restrict__ x, const float* __restrict__ w) {
    const int b = blockIdx.x;
    const int tid = threadIdx.x;
    if (b < 4096) {
        int i = b * 256 + tid;                  // float4 index
        float4 v = ((const float4*)x)[i];
        __half2 a = __floats2half2_rn(v.x, v.y);
        __half2 c = __floats2half2_rn(v.z, v.w);
        ((__half2*)g_xf)[2 * i]     = a;
        ((__half2*)g_xf)[2 * i + 1] = c;
    } else {
        __shared__ float t[32][33];
        int wb = b - 4096;                      // 0..3071 = 96 x 32
        int nb = (wb % 96) * 32, kb = (wb / 96) * 32;
        int tx = tid & 31, ty = tid >> 5;       // (32, 8)
        #pragma unroll
        for (int r = ty; r < 32; r += 8)
            t[r][tx] = w[(size_t)(kb + r) * N_TOT + nb + tx];
        __syncthreads();
        #pragma unroll
        for (int r = ty; r < 32; r += 8)
            g_wtf[(size_t)(nb + r) * K_TOT + kb + tx] = __float2half_rn(t[tx][r]);
    }
}

// ---------------------------------------------------------------------------
// HMMA QKV GEMM (fp16 1-term): CTA 128(M) x 128(N), 4 warps (warp 64x64),
// 128 threads, k-chunk 64 (128B rows, XOR swizzle), 3-stage cp.async pipeline,
// 2 CTAs/SM. LDSM:MMA = 8:32 per kh step (was 6:16).
// Epilogue: Q/K/V -> single fp16 planes [B,H,T,D]; Q scaled by 0.125*log2e.
// ---------------------------------------------------------------------------
#define OFF_A 0
#define OFF_B 16384
#define BUF_B 32768

__global__ __launch_bounds__(128, 2) void qkv_tc(const float* __restrict__ bias) {
    extern __shared__ __align__(1024) char smem[];
    const uint32_t sbase = smem_u32(smem);
    const int tid  = threadIdx.x;
    const int lane = tid & 31;
    const int wid  = tid >> 5;
    const int wm   = wid >> 1;        // 0..1 (m 64-blocks)
    const int wn   = wid & 1;         // 0..1 (n 64-blocks)
    const int bnB  = blockIdx.x;      // 0..23
    const int bmB  = blockIdx.y;      // 0..31

    const __half* Xf = g_xf  + (size_t)(bmB * 128) * K_TOT;
    const __half* Wf = g_wtf + (size_t)(bnB * 128) * K_TOT;

    auto load_tiles = [&](int ch, int buf) {
        uint32_t sb = sbase + buf * BUF_B;
        #pragma unroll
        for (int it = 0; it < 8; it++) {          // A: 128 rows x 128B
            int f = it * 128 + tid;
            int r = f >> 3, c = f & 7;
            cp_async16(sb + OFF_A + SWZ(r, c), Xf + (size_t)r * K_TOT + ch * 64 + c * 8);
        }
        #pragma unroll
        for (int it = 0; it < 8; it++) {          // B: 128 rows x 128B
            int f = it * 128 + tid;
            int r = f >> 3, c = f & 7;
            cp_async16(sb + OFF_B + SWZ(r, c), Wf + (size_t)r * K_TOT + ch * 64 + c * 8);
        }
        CP_COMMIT();
    };

    float acc[4][8][4];   // [am 16-row][bn 8-col][frag]
    #pragma unroll
    for (int i = 0; i < 4; i++)
        #pragma unroll
        for (int j = 0; j < 8; j++)
            #pragma unroll
            for (int c = 0; c < 4; c++) acc[i][j][c] = 0.f;

    load_tiles(0, 0);
    load_tiles(1, 1);

    const int NCH = K_TOT / 64;   // 16
    for (int ch = 0; ch < NCH; ch++) {
        const int buf = ch % 3;
        if (ch + 2 < NCH) { load_tiles(ch + 2, (ch + 2) % 3); CP_WAIT(2); }
        else if (ch + 1 < NCH) { CP_WAIT(1); }
        else { CP_WAIT(0); }
        __syncthreads();

        const uint32_t sbuf = sbase + buf * BUF_B;
        #pragma unroll
        for (int kh = 0; kh < 4; kh++) {
            uint32_t ah[4][4];
            #pragma unroll
            for (int am = 0; am < 4; am++) {
                int row = wm * 64 + am * 16 + (lane & 15);
                int chn = kh * 2 + (lane >> 4);
                ldsm_x4(ah[am][0], ah[am][1], ah[am][2], ah[am][3],
                        sbuf + OFF_A + SWZ(row, chn));
            }
            #pragma unroll
            for (int bp = 0; bp < 4; bp++) {
                int row = wn * 64 + bp * 16 + ((lane >> 4) << 3) + (lane & 7);
                int chn = kh * 2 + ((lane >> 3) & 1);
                uint32_t b0, b1, b2, b3;
                ldsm_x4(b0, b1, b2, b3, sbuf + OFF_B + SWZ(row, chn));
                const int nA = bp * 2, nB = nA + 1;
                #pragma unroll
                for (int am = 0; am < 4; am++) MMA4H(acc[am][nA], ah[am], b0, b1);
                #pragma unroll
                for (int am = 0; am < 4; am++) MMA4H(acc[am][nB], ah[am], b2, b3);
            }
        }
        __syncthreads();
    }

    // Epilogue: bias; Q scaled by 0.125*log2e; Q/K/V -> single fp16 planes.
    const int mq = lane >> 2;
    const int nq = (lane & 3) * 2;
    const int nbase = bnB * 128 + wn * 64;       // 64-aligned: p uniform per warp
    const int p = nbase >> 10;
    __half* dst = (p == 0) ? g_qf : (p == 1) ? g_kf : g_vf;
    const float sc = (p == 0) ? 0.18033688011112042f : 1.0f;   // 0.125*log2(e)

    #pragma unroll
    for (int bn = 0; bn < 8; bn++) {
        int n = nbase + bn * 8 + nq;
        float2 bb = *(const float2*)(bias + n);
        int cc = n & 1023;
        int hh = cc >> 6, d = cc & 63;
        #pragma unroll
        for (int am = 0; am < 4; am++) {
            #pragma unroll
            for (int half = 0; half < 2; half++) {
                int m = bmB * 128 + wm * 64 + am * 16 + mq + half * 8;
                int bi = m >> 11, t = m & 2047;
                float vx = (acc[am][bn][half * 2]     + bb.x) * sc;
                float vy = (acc[am][bn][half * 2 + 1] + bb.y) * sc;
                __half2 hv = __floats2half2_rn(vx, vy);
                size_t idx = ((size_t)(bi * NH + hh) * SEQ + t) * HD + d;
                *(uint32_t*)(dst + idx) = *reinterpret_cast<uint32_t*>(&hv);
            }
        }
    }
}

// ---------------------------------------------------------------------------
// Tensor-core flash attention (R16 config — best measured 73.2us, unchanged).
// fp16 1-term S and PV, exp2 domain, BK=128 blocks, 2 KV buffers, 3 CTAs/SM.
// CTA: 64 Q rows, 4 warps. LPT.
// ---------------------------------------------------------------------------
#define KVT2   16384            // one 128-row x 128B plane
#define KVBUF  (2 * KVT2)       // Kf, Vf = 32768
#define KVOFF  8192             // after Qf (8192)
#define ATTN_SMEM (KVOFF + 2 * KVBUF)   // 73728

__global__ __launch_bounds__(128, 3) void attn_mma(float* __restrict__ out) {
    extern __shared__ __align__(1024) char smem[];
    const uint32_t sb = smem_u32(smem);
    const int tid = threadIdx.x, lane = tid & 31, wid = tid >> 5;
    const int qt = (int)gridDim.x - 1 - (int)blockIdx.x;   // LPT: heavy first
    const int hh = blockIdx.y, bb = blockIdx.z;

    const size_t head = (size_t)(bb * NH + hh) * SEQ * HD;
    const char* Qfg = (const char*)(g_qf + head + (size_t)qt * 64 * HD);
    const char* Kfg = (const char*)(g_kf + head);
    const char* Vfg = (const char*)(g_vf + head);

    // Q -> smem (64 rows x 128B)
    #pragma unroll
    for (int i = 0; i < 4; i++) {
        int f = i * 128 + tid;
        int r = f >> 3, c = f & 7;
        cp_async16(sb + SWZ(r, c), Qfg + r * 128 + c * 16);
    }
    CP_COMMIT();

    // Load one 128-row K/V block
    auto load_kv = [&](int kt, int buf) {
        uint32_t base = sb + KVOFF + buf * KVBUF;
        size_t go0 = (size_t)kt * 128 * 128;     // 128 rows x 128 B
        #pragma unroll
        for (int i = 0; i < 8; i++) {
            int f = i * 128 + tid;
            int r = f >> 3, c = f & 7;
            uint32_t sw = SWZ(r, c);
            size_t go = go0 + r * 128 + c * 16;
            cp_async16(base + sw,        Kfg + go);
            cp_async16(base + KVT2 + sw, Vfg + go);
        }
        CP_COMMIT();
    };

    const int nkt = (qt + 2) >> 1;   // ceil((qt+1)*64 / 128)
    load_kv(0, 0);
    CP_WAIT(0);
    __syncthreads();

    // Q fragments (resident)
    uint32_t qf[4][4];
    {
        int row = wid * 16 + (lane & 15);
        #pragma unroll
        for (int ks = 0; ks < 4; ks++) {
            int chn = ks * 2 + (lane >> 4);
            ldsm_x4(qf[ks][0], qf[ks][1], qf[ks][2], qf[ks][3], sb + SWZ(row, chn));
        }
    }

    float o[8][4];
    #pragma unroll
    for (int nt = 0; nt < 8; nt++)
        #pragma unroll
        for (int c = 0; c < 4; c++) o[nt][c] = 0.f;
    float m0 = -1e30f, m1 = -1e30f, l0 = 0.f, l1 = 0.f;

    const int grow = qt * 64 + wid * 16 + (lane >> 2);   // global Q row (and +8)

    for (int kt = 0; kt < nkt; kt++) {
        const int buf = kt & 1;
        const bool has_next = (kt + 1 < nkt);
        if (has_next) load_kv(kt + 1, buf ^ 1);   // async, lands during compute

        // ---- S = Q K^T over 128 K rows (16 n-tiles of 8 cols) ----
        float sA[16][4];
        {
            uint32_t kbase = sb + KVOFF + buf * KVBUF;
            const int krbase = ((lane >> 4) << 3) + (lane & 7);
            #pragma unroll
            for (int ks = 0; ks < 4; ks++) {
                const int chn = ks * 2 + ((lane >> 3) & 1);
                #pragma unroll
                for (int rg = 0; rg < 8; rg++) {
                    uint32_t k0, k1, k2, k3;
                    ldsm_x4(k0, k1, k2, k3, kbase + SWZ(rg * 16 + krbase, chn));
                    if (ks == 0) {
                        MMA4HI(sA[rg * 2],     qf[0], k0, k1);
                        MMA4HI(sA[rg * 2 + 1], qf[0], k2, k3);
                    } else {
                        MMA4H(sA[rg * 2],     qf[ks], k0, k1);
                        MMA4H(sA[rg * 2 + 1], qf[ks], k2, k3);
                    }
                }
            }
        }

        // ---- causal mask (last block only) ----
        if (kt == nkt - 1) {
            #pragma unroll
            for (int nt = 0; nt < 16; nt++) {
                int j0 = kt * 128 + nt * 8 + (lane & 3) * 2;
                if (j0     > grow)     sA[nt][0] = -1e30f;
                if (j0 + 1 > grow)     sA[nt][1] = -1e30f;
                if (j0     > grow + 8) sA[nt][2] = -1e30f;
                if (j0 + 1 > grow + 8) sA[nt][3] = -1e30f;
            }
        }

        // ---- online softmax in exp2 domain (rows grow, grow+8) ----
        float mx0 = -1e30f, mx1 = -1e30f;
        #pragma unroll
        for (int nt = 0; nt < 16; nt++) {
            mx0 = fmaxf(mx0, fmaxf(sA[nt][0], sA[nt][1]));
            mx1 = fmaxf(mx1, fmaxf(sA[nt][2], sA[nt][3]));
        }
        mx0 = fmaxf(mx0, __shfl_xor_sync(0xffffffffu, mx0, 1));
        mx0 = fmaxf(mx0, __shfl_xor_sync(0xffffffffu, mx0, 2));
        mx1 = fmaxf(mx1, __shfl_xor_sync(0xffffffffu, mx1, 1));
        mx1 = fmaxf(mx1, __shfl_xor_sync(0xffffffffu, mx1, 2));
        float mn0 = fmaxf(m0, mx0), mn1 = fmaxf(m1, mx1);
        bool resc = (mn0 > m0) || (mn1 > m1);

        float t0 = 0.f, t1 = 0.f;
        #pragma unroll
        for (int nt = 0; nt < 16; nt++) {
            sA[nt][0] = ex2f(sA[nt][0] - mn0); t0 += sA[nt][0];
            sA[nt][1] = ex2f(sA[nt][1] - mn0); t0 += sA[nt][1];
            sA[nt][2] = ex2f(sA[nt][2] - mn1); t1 += sA[nt][2];
            sA[nt][3] = ex2f(sA[nt][3] - mn1); t1 += sA[nt][3];
        }
        t0 += __shfl_xor_sync(0xffffffffu, t0, 1);
        t0 += __shfl_xor_sync(0xffffffffu, t0, 2);
        t1 += __shfl_xor_sync(0xffffffffu, t1, 1);
        t1 += __shfl_xor_sync(0xffffffffu, t1, 2);
        if (__any_sync(0xffffffffu, resc)) {
            float cr0 = ex2f(m0 - mn0), cr1 = ex2f(m1 - mn1);
            l0 = l0 * cr0 + t0;
            l1 = l1 * cr1 + t1;
            #pragma unroll
            for (int nt = 0; nt < 8; nt++) {
                o[nt][0] *= cr0; o[nt][1] *= cr0;
                o[nt][2] *= cr1; o[nt][3] *= cr1;
            }
        } else {
            l0 += t0; l1 += t1;
        }
        m0 = mn0; m1 = mn1;

        // ---- O += P V over 128 V rows (8 k-groups of 16) ----
        {
            uint32_t vbase = sb + KVOFF + buf * KVBUF + KVT2;
            const int vrbase = ((lane >> 3) & 1) * 8 + (lane & 7);
            #pragma unroll
            for (int t = 0; t < 8; t++) {
                uint32_t ph[4];
                {
                    __half2 a = __floats2half2_rn(sA[2 * t][0],     sA[2 * t][1]);
                    __half2 b = __floats2half2_rn(sA[2 * t][2],     sA[2 * t][3]);
                    __half2 c = __floats2half2_rn(sA[2 * t + 1][0], sA[2 * t + 1][1]);
                    __half2 d = __floats2half2_rn(sA[2 * t + 1][2], sA[2 * t + 1][3]);
                    ph[0] = *reinterpret_cast<uint32_t*>(&a);
                    ph[1] = *reinterpret_cast<uint32_t*>(&b);
                    ph[2] = *reinterpret_cast<uint32_t*>(&c);
                    ph[3] = *reinterpret_cast<uint32_t*>(&d);
                }
                const int vrow = t * 16 + vrbase;
                #pragma unroll
                for (int gp = 0; gp < 2; gp++) {
                    const int g0 = gp * 2, g1 = gp * 2 + 1;
                    uint32_t sw0 = SWZ(vrow, g0 * 2 + (lane >> 4));
                    uint32_t sw1 = SWZ(vrow, g1 * 2 + (lane >> 4));
                    uint32_t v0, v1, v2, v3, u0, u1, u2, u3;
                    ldsm_x4_t(v0, v1, v2, v3, vbase + sw0);
                    ldsm_x4_t(u0, u1, u2, u3, vbase + sw1);
                    MMA4H(o[2 * g0],     ph, v0, v1);
                    MMA4H(o[2 * g0 + 1], ph, v2, v3);
                    MMA4H(o[2 * g1],     ph, u0, u1);
                    MMA4H(o[2 * g1 + 1], ph, u2, u3);
                }
            }
        }

        if (has_next) {
            CP_WAIT(0);          // kv(kt+1) landed
            __syncthreads();     // all warps done reading buf before reuse
        }
    }

    // ---- epilogue ----
    float il0 = 1.f / l0, il1 = 1.f / l1;
    #pragma unroll
    for (int nt = 0; nt < 8; nt++) {
        int d = nt * 8 + (lane & 3) * 2;
        float2 u0 = make_float2(o[nt][0] * il0, o[nt][1] * il0);
        float2 u1 = make_float2(o[nt][2] * il1, o[nt][3] * il1);
        *(float2*)(out + ((size_t)(bb * SEQ + grow)     * EMB) + hh * 64 + d) = u0;
        *(float2*)(out + ((size_t)(bb * SEQ + grow + 8) * EMB) + hh * 64 + d) = u1;
    }
}

// ---------------------------------------------------------------------------
extern "C" void kernel_launch(void* const* d_in, const int* in_sizes, int n_in,
                              void* d_out, int out_size) {
    const float* x    = (const float*)d_in[0];
    const float* w    = (const float*)d_in[1];
    const float* bias = (const float*)d_in[2];
    float* out = (float*)d_out;

    conv_xw<<<4096 + 3072, 256>>>(x, w);

    const int gemm_smem = 3 * BUF_B;   // 98304 B
    cudaFuncSetAttribute(qkv_tc, cudaFuncAttributeMaxDynamicSharedMemorySize, gemm_smem);
    qkv_tc<<<dim3(N_TOT / 128, M_TOT / 128), 128, gemm_smem>>>(bias);

    cudaFuncSetAttribute(attn_mma, cudaFuncAttributeMaxDynamicSharedMemorySize, ATTN_SMEM);
    attn_mma<<<dim3(SEQ / 64, NH, BATCH), 128, ATTN_SMEM>>>(out);
}